// round 14
// baseline (speedup 1.0000x reference)
#include <cuda_runtime.h>
#include <cuda_bf16.h>
#include <cstdint>

#define NB   32
#define NN   4096
#define DM   64

// scratch (allocation-free: device globals)
__device__ uint32_t g_yb[NB * 2 * DM * (NN / 2)];  // y bf16x2: [b][s*64+o][k/2]  32 MB
__device__ uint32_t g_ab[2 * NN * (NN / 2)];       // adj bf16x2: [s][w][k/2]     67 MB

__device__ __forceinline__ uint32_t pack_bf16(float lo, float hi) {
    uint32_t r;
    asm("cvt.rn.bf16x2.f32 %0, %1, %2;" : "=r"(r) : "f"(hi), "f"(lo));
    return r;
}

#define MMA_BF16(c, a, b)                                                    \
    asm volatile("mma.sync.aligned.m16n8k16.row.col.f32.bf16.bf16.f32 "      \
                 "{%0,%1,%2,%3}, {%4,%5,%6,%7}, {%8,%9}, {%0,%1,%2,%3};"     \
                 : "+f"((c)[0]), "+f"((c)[1]), "+f"((c)[2]), "+f"((c)[3])    \
                 : "r"((a)[0]), "r"((a)[1]), "r"((a)[2]), "r"((a)[3]),       \
                   "r"((b)[0]), "r"((b)[1]))

#define LDSM_X4(r0, r1, r2, r3, addr)                                        \
    asm volatile("ldmatrix.sync.aligned.m8n8.x4.shared.b16 {%0,%1,%2,%3}, [%4];" \
                 : "=r"(r0), "=r"(r1), "=r"(r2), "=r"(r3) : "r"(addr))

#define CP_ASYNC16(dst, src)                                                 \
    asm volatile("cp.async.cg.shared.global [%0], [%1], 16;"                 \
                 :: "r"(dst), "l"(src) : "memory")
#define CP_COMMIT()  asm volatile("cp.async.commit_group;" ::: "memory")
#define CP_WAIT3()   asm volatile("cp.async.wait_group 3;" ::: "memory")
#define CP_WAIT0()   asm volatile("cp.async.wait_group 0;" ::: "memory")

// ---------------------------------------------------------------------------
// Kernel P: adj float -> bf16 (g_ab)
// ---------------------------------------------------------------------------
__global__ __launch_bounds__(256) void kernP(const float* __restrict__ adj)
{
    const size_t u = ((size_t)blockIdx.x * 256 + threadIdx.x) * 4;
    const float4* s = (const float4*)(adj + u * 2);
    float4 v0 = s[0], v1 = s[1];
    uint4 t;
    t.x = pack_bf16(v0.x, v0.y); t.y = pack_bf16(v0.z, v0.w);
    t.z = pack_bf16(v1.x, v1.y); t.w = pack_bf16(v1.z, v1.w);
    *(uint4*)(g_ab + u) = t;
}

// ---------------------------------------------------------------------------
// Kernel A (bf16 mma): y[b, r=s*64+o, v] = sum_c W_mlp[o, s*65+c] * xin[b,c,v]
// ---------------------------------------------------------------------------
#define PA 44

__global__ __launch_bounds__(256, 2) void kernA_mma(const float* __restrict__ x,
                                                    const float* __restrict__ h,
                                                    const float* __restrict__ Wm)
{
    __shared__ uint32_t Ws[128 * PA];
    __shared__ uint32_t Xs[128 * PA];
    const int tid  = threadIdx.x;
    const int wid  = tid >> 5, lane = tid & 31;
    const int wm   = wid & 1, wn = wid >> 1;
    const int b    = blockIdx.y;
    const int v0   = blockIdx.x * 128;

    for (int i = tid; i < 128 * PA; i += 256) { Ws[i] = 0u; Xs[i] = 0u; }
    __syncthreads();

    uint16_t* Wh = (uint16_t*)Ws;
    uint16_t* Xh = (uint16_t*)Xs;

    for (int idx = tid; idx < 128 * 65; idx += 256) {
        int r = idx / 65, c = idx - r * 65;
        int s = r >> 6, o = r & 63;
        float w = Wm[o * 130 + s * 65 + c];
        Wh[r * (PA * 2) + c] = (uint16_t)pack_bf16(w, 0.0f);
    }
    for (int idx = tid; idx < 65 * 128; idx += 256) {
        int c = idx >> 7, v = idx & 127;
        float val;
        if (c == 0) val = x[(size_t)b * NN + v0 + v];
        else        val = h[((size_t)b * DM + (c - 1)) * NN + v0 + v];
        Xh[v * (PA * 2) + c] = (uint16_t)pack_bf16(val, 0.0f);
    }
    __syncthreads();

    float c[4][4][4];
#pragma unroll
    for (int i = 0; i < 4; i++)
#pragma unroll
        for (int j = 0; j < 4; j++)
#pragma unroll
            for (int q = 0; q < 4; q++) c[i][j][q] = 0.0f;

    const uint32_t Abase = (uint32_t)__cvta_generic_to_shared(Ws);
    const uint32_t Bbase = (uint32_t)__cvta_generic_to_shared(Xs);
    const uint32_t aoff  = (uint32_t)((wm * 64 + (lane & 15)) * PA + (lane >> 4) * 4);
    const int bt = lane >> 3;
    const uint32_t boff  = (uint32_t)((wn * 32 + (lane & 7) + ((bt >> 1) * 8)) * PA
                                      + (bt & 1) * 4);

#pragma unroll
    for (int kk = 0; kk < 5; kk++) {
        uint32_t a[4][4], bfr[4][2];
#pragma unroll
        for (int mi = 0; mi < 4; mi++) {
            uint32_t ad = Abase + (aoff + mi * 16 * PA + kk * 8) * 4;
            LDSM_X4(a[mi][0], a[mi][1], a[mi][2], a[mi][3], ad);
        }
#pragma unroll
        for (int nj = 0; nj < 2; nj++) {
            uint32_t bd = Bbase + (boff + nj * 16 * PA + kk * 8) * 4;
            LDSM_X4(bfr[nj * 2][0], bfr[nj * 2][1],
                    bfr[nj * 2 + 1][0], bfr[nj * 2 + 1][1], bd);
        }
#pragma unroll
        for (int mi = 0; mi < 4; mi++)
#pragma unroll
            for (int ni = 0; ni < 4; ni++)
                MMA_BF16(c[mi][ni], a[mi], bfr[ni]);
    }

    const int r2 = lane >> 2, cc2 = lane & 3;
#pragma unroll
    for (int mi = 0; mi < 4; mi++) {
        const int mrow = wm * 64 + mi * 16 + r2;
#pragma unroll
        for (int ni = 0; ni < 4; ni++) {
            const int vu = (v0 >> 1) + wn * 16 + ni * 4 + cc2;
            g_yb[((size_t)b * 128 + mrow) * (NN / 2) + vu] =
                pack_bf16(c[mi][ni][0], c[mi][ni][1]);
            g_yb[((size_t)b * 128 + mrow + 8) * (NN / 2) + vu] =
                pack_bf16(c[mi][ni][2], c[mi][ni][3]);
        }
    }
}

// ---------------------------------------------------------------------------
// Kernel B: PERSISTENT bf16 mma (cp.async 5-stage + ldmatrix) + fused epilogue.
// 296 CTAs, each loops tiles (tile = m-fastest: m0=(t&15)*128, w0=(t>>4)*128).
// ---------------------------------------------------------------------------
#define PITCH   20
#define OPER    (128 * PITCH)
#define STAGEU  (2 * OPER)
#define NSTAGE  5
#define ZB_OFF  0
#define WT_OFF  16896
#define WR_OFF  (WT_OFF + 8704)
#define RED_OFF (WR_OFF + 128)       // 25728 (outside stage region 0..25600)
#define BM_OFF  (RED_OFF + 256)
#define BL_OFF  (BM_OFF + 64)
#define SMEMB   ((BL_OFF + 64) * 4)
#define NTILE   512
#define NPERS   296

__global__ __launch_bounds__(256, 2) void kernB_mma(const float* __restrict__ h,
                                                    const float* __restrict__ Wl,
                                                    const float* __restrict__ bl,
                                                    const float* __restrict__ Wr,
                                                    const float* __restrict__ br,
                                                    const float* __restrict__ bm,
                                                    const float* __restrict__ pa,
                                                    float* __restrict__ out)
{
    extern __shared__ uint32_t smb[];
    const uint32_t smem0 = (uint32_t)__cvta_generic_to_shared(smb);

    const int tid  = threadIdx.x;
    const int wid  = tid >> 5, lane = tid & 31;
    const int wm   = wid & 1;
    const int wn   = wid >> 1;

    const int lr  = tid >> 2;
    const int ci  = tid & 3;
    const uint32_t dA0 = lr * PITCH + ci * 4, dA1 = (lr + 64) * PITCH + ci * 4;

    const uint32_t aoff = (uint32_t)((wm * 64 + (lane & 15)) * PITCH + (lane >> 4) * 4);
    const int bt   = lane >> 3;
    const uint32_t boff = (uint32_t)((wn * 32 + (lane & 7) + ((bt >> 1) * 8)) * PITCH
                                     + (bt & 1) * 4);
    const int ty = tid >> 4, tx = tid & 15;

    for (int tile = blockIdx.x; tile < NTILE; tile += NPERS) {
        const int m0 = (tile & 15) * 128;
        const int w0 = (tile >> 4) * 128;
        const int b0 = (tile & 15) * 2;

        float c[4][4][4];
#pragma unroll
        for (int i = 0; i < 4; i++)
#pragma unroll
            for (int j = 0; j < 4; j++)
#pragma unroll
                for (int q = 0; q < 4; q++) c[i][j][q] = 0.0f;

        const int mA0 = m0 + lr, mA1 = m0 + lr + 64;
        const size_t yb0 = ((size_t)(mA0 >> 6) * 128 + (mA0 & 63)) * (NN / 2) + ci * 4;
        const size_t yb1 = ((size_t)(mA1 >> 6) * 128 + (mA1 & 63)) * (NN / 2) + ci * 4;
        const size_t ab0 = (size_t)(w0 + lr) * (NN / 2) + ci * 4;
        const size_t ab1 = (size_t)(w0 + lr + 64) * (NN / 2) + ci * 4;

        auto issue_stage = [&](int it, int st) {
            const int s   = it >> 7;
            const int k0u = (it & 127) << 4;
            const size_t ys = (size_t)s * 64 * (NN / 2) + k0u;
            const size_t as = (size_t)s * NN * (NN / 2) + k0u;
            const uint32_t base = smem0 + st * (STAGEU * 4);
            CP_ASYNC16(base + dA0 * 4,          (const void*)(g_yb + yb0 + ys));
            CP_ASYNC16(base + dA1 * 4,          (const void*)(g_yb + yb1 + ys));
            CP_ASYNC16(base + (OPER + dA0) * 4, (const void*)(g_ab + ab0 + as));
            CP_ASYNC16(base + (OPER + dA1) * 4, (const void*)(g_ab + ab1 + as));
        };

        issue_stage(0, 0); CP_COMMIT();
        issue_stage(1, 1); CP_COMMIT();
        issue_stage(2, 2); CP_COMMIT();
        issue_stage(3, 3); CP_COMMIT();

        for (int it = 0; it < 256; ++it) {
            CP_WAIT3();
            __syncthreads();
            if (it + 4 < 256) issue_stage(it + 4, (it + 4) % NSTAGE);
            CP_COMMIT();

            const uint32_t Ab = smem0 + (it % NSTAGE) * (STAGEU * 4);
            const uint32_t Bb = Ab + OPER * 4;

#pragma unroll
            for (int kk = 0; kk < 2; kk++) {
                uint32_t a[4][4], bfr[4][2];
#pragma unroll
                for (int mi = 0; mi < 4; mi++) {
                    uint32_t ad = Ab + (aoff + mi * 16 * PITCH + kk * 8) * 4;
                    LDSM_X4(a[mi][0], a[mi][1], a[mi][2], a[mi][3], ad);
                }
#pragma unroll
                for (int nj = 0; nj < 2; nj++) {
                    uint32_t bd = Bb + (boff + nj * 16 * PITCH + kk * 8) * 4;
                    LDSM_X4(bfr[nj * 2][0], bfr[nj * 2][1],
                            bfr[nj * 2 + 1][0], bfr[nj * 2 + 1][1], bd);
                }
#pragma unroll
                for (int mi = 0; mi < 4; mi++)
#pragma unroll
                    for (int ni = 0; ni < 4; ni++)
                        MMA_BF16(c[mi][ni], a[mi], bfr[ni]);
            }
        }

        // ---- drain outstanding cp.async groups, then reuse smem ----
        CP_WAIT0();
        __syncthreads();

        float* Zbf  = (float*)(smb + ZB_OFF);
        float* Wtf  = (float*)(smb + WT_OFF);
        float* wr_s = (float*)(smb + WR_OFF);
        float* redf = (float*)(smb + RED_OFF);
        float* bm_s = (float*)(smb + BM_OFF);
        float* bl_s = (float*)(smb + BL_OFF);

        {
            const int r = lane >> 2, cc2 = (lane & 3) * 2;
#pragma unroll
            for (int mi = 0; mi < 4; mi++) {
                const int row = wm * 64 + mi * 16 + r;
#pragma unroll
                for (int ni = 0; ni < 4; ni++) {
                    const int col = wn * 32 + ni * 8 + cc2;
                    Zbf[row * 132 + col]           = c[mi][ni][0];
                    Zbf[row * 132 + col + 1]       = c[mi][ni][1];
                    Zbf[(row + 8) * 132 + col]     = c[mi][ni][2];
                    Zbf[(row + 8) * 132 + col + 1] = c[mi][ni][3];
                }
            }
        }
        for (int idx = tid; idx < 8192; idx += 256) {
            int o = idx >> 7, k = idx & 127;
            Wtf[k * 68 + o] = Wl[o * 128 + k];
        }
        if (tid < 128) wr_s[tid] = Wr[tid];
        if (tid < 64)  { bm_s[tid] = bm[tid]; bl_s[tid] = bl[tid]; }
        redf[tid] = 0.0f;
        __syncthreads();

        float acc2[2][4][8];
#pragma unroll
        for (int i = 0; i < 4; i++) {
            float bv = bl_s[ty * 4 + i];
#pragma unroll
            for (int j = 0; j < 8; j++) { acc2[0][i][j] = bv; acc2[1][i][j] = bv; }
        }

#pragma unroll 4
        for (int k = 0; k < 64; k++) {
            float4 wv = *(const float4*)&Wtf[k * 68 + ty * 4];
            float wf[4] = {wv.x, wv.y, wv.z, wv.w};
            float bmk = bm_s[k];
#pragma unroll
            for (int bb = 0; bb < 2; bb++) {
                float4 z0 = *(const float4*)&Zbf[(bb * 64 + k) * 132 + tx * 8];
                float4 z1 = *(const float4*)&Zbf[(bb * 64 + k) * 132 + tx * 8 + 4];
                float in[8] = {z0.x + bmk, z0.y + bmk, z0.z + bmk, z0.w + bmk,
                               z1.x + bmk, z1.y + bmk, z1.z + bmk, z1.w + bmk};
#pragma unroll
                for (int i = 0; i < 4; i++)
#pragma unroll
                    for (int j = 0; j < 8; j++) acc2[bb][i][j] += wf[i] * in[j];
            }
        }
        __syncthreads();

        for (int idx = tid; idx < 16384; idx += 256) {
            int row = idx >> 7, v = idx & 127;
            Zbf[row * 132 + v] =
                h[((size_t)(b0 + (row >> 6)) * DM + (row & 63)) * NN + w0 + v];
        }
        __syncthreads();

#pragma unroll 4
        for (int k = 0; k < 64; k++) {
            float4 wv = *(const float4*)&Wtf[(64 + k) * 68 + ty * 4];
            float wf[4] = {wv.x, wv.y, wv.z, wv.w};
#pragma unroll
            for (int bb = 0; bb < 2; bb++) {
                float4 z0 = *(const float4*)&Zbf[(bb * 64 + k) * 132 + tx * 8];
                float4 z1 = *(const float4*)&Zbf[(bb * 64 + k) * 132 + tx * 8 + 4];
                float in[8] = {z0.x, z0.y, z0.z, z0.w, z1.x, z1.y, z1.z, z1.w};
#pragma unroll
                for (int i = 0; i < 4; i++)
#pragma unroll
                    for (int j = 0; j < 8; j++) acc2[bb][i][j] += wf[i] * in[j];
            }
        }

        const float slope = pa[0];
        float* out2 = out + (size_t)NB * NN;
#pragma unroll
        for (int bb = 0; bb < 2; bb++) {
            const int b = b0 + bb;
            float part[8];
#pragma unroll
            for (int j = 0; j < 8; j++) part[j] = 0.0f;
#pragma unroll
            for (int i = 0; i < 4; i++) {
                const int o = ty * 4 + i;
                const float wro = wr_s[o], wrh = wr_s[64 + o];
                float p[8], hv[8];
#pragma unroll
                for (int j = 0; j < 8; j++) {
                    float v = acc2[bb][i][j];
                    p[j] = (v >= 0.0f) ? v : slope * v;
                    part[j] += wro * p[j];
                    hv[j] = Zbf[(bb * 64 + o) * 132 + tx * 8 + j];
                    part[j] += wrh * hv[j];
                }
                float* dst = &out2[((size_t)b * 128 + o) * NN + w0 + tx * 8];
                *(float4*)dst       = make_float4(p[0], p[1], p[2], p[3]);
                *(float4*)(dst + 4) = make_float4(p[4], p[5], p[6], p[7]);
                float* dsth = &out2[((size_t)b * 128 + 64 + o) * NN + w0 + tx * 8];
                *(float4*)dsth       = make_float4(hv[0], hv[1], hv[2], hv[3]);
                *(float4*)(dsth + 4) = make_float4(hv[4], hv[5], hv[6], hv[7]);
            }
#pragma unroll
            for (int j = 0; j < 8; j++)
                atomicAdd(&redf[bb * 128 + tx * 8 + j], part[j]);
        }
        __syncthreads();
        {
            const int bb = tid >> 7, v = tid & 127;
            out[(size_t)(b0 + bb) * NN + w0 + v] = redf[tid] + br[0];
        }
        // redf region (u32 25728+) is outside stage buffers (0..25600),
        // so next tile's prologue cp.asyncs can't race the reads above.
    }
}

// ---------------------------------------------------------------------------
extern "C" void kernel_launch(void* const* d_in, const int* in_sizes, int n_in,
                              void* d_out, int out_size)
{
    const float* x   = (const float*)d_in[0];
    const float* h   = (const float*)d_in[1];
    const float* adj = (const float*)d_in[2];
    const float* Wm  = (const float*)d_in[3];
    const float* bm  = (const float*)d_in[4];
    const float* Wl  = (const float*)d_in[5];
    const float* bl  = (const float*)d_in[6];
    const float* Wr  = (const float*)d_in[7];
    const float* br  = (const float*)d_in[8];
    const float* pa  = (const float*)d_in[9];
    float* out = (float*)d_out;

    cudaFuncSetAttribute(kernB_mma, cudaFuncAttributeMaxDynamicSharedMemorySize, SMEMB);

    kernP<<<2 * NN * (NN / 2) / (256 * 4), 256>>>(adj);
    kernA_mma<<<dim3(NN / 128, NB), 256>>>(x, h, Wm);
    kernB_mma<<<NPERS, 256, SMEMB>>>(h, Wl, bl, Wr, br, bm, pa, out);
}